// round 2
// baseline (speedup 1.0000x reference)
#include <cuda_runtime.h>
#include <math.h>
#include <stdint.h>

#define NPOS    80
#define HID     128
#define TILE    64      // rows per CTA
#define THREADS 256

// Shared memory layout (dynamic, 128 KB):
//   [0      , 65536)  : Wsh  (current layer weights, 128x128 f32) -- aliased by msg bytes during gather
//   [65536  , 98304)  : hA   (64 x 128 f32)
//   [98304  , 131072) : hB   (64 x 128 f32)
#define SMEM_BYTES (65536 + 32768 + 32768)

__device__ int g_msg_is64;

// Detect whether the message buffer is int64 (odd int32 words all zero) or int32.
__global__ void detect_kernel(const int* __restrict__ msg) {
    int t = threadIdx.x;
    int v = 0;
    #pragma unroll 4
    for (int i = t; i < 2048; i += 32) v |= msg[2 * i + 1];
    unsigned ball = __ballot_sync(0xFFFFFFFFu, v != 0);
    if (t == 0) g_msg_is64 = (ball == 0u) ? 1 : 0;
}

__device__ __forceinline__ float elu1(float x) {
    return x > 0.0f ? x : expm1f(x);
}

__global__ __launch_bounds__(THREADS, 1)
void fused_kernel(const int* __restrict__ msg,
                  const float* __restrict__ W1, const float* __restrict__ b1,
                  const float* __restrict__ W2, const float* __restrict__ b2,
                  const float* __restrict__ W3, const float* __restrict__ b3,
                  const float* __restrict__ W4, const float* __restrict__ b4,
                  float* __restrict__ out, int B)
{
    extern __shared__ float smem[];
    float* Wsh = smem;                       // 16384 floats
    float* hA  = smem + 16384;               // 8192 floats
    float* hB  = smem + 16384 + 8192;        // 8192 floats
    unsigned char* msg_sh = (unsigned char*)smem;  // 5120 bytes, aliases Wsh

    const int t    = threadIdx.x;
    const int row0 = blockIdx.x * TILE;
    const int is64 = g_msg_is64;

    // ---- Stage message tile as bytes, layout [p][r] ----
    for (int idx = t; idx < NPOS * TILE; idx += THREADS) {
        int p = idx >> 6;         // position 0..79
        int r = idx & 63;         // local row
        int row = row0 + r;
        int c = 0;
        if (row < B) {
            int gi = row * NPOS + p;
            c = is64 ? msg[2 * gi] : msg[gi];
        }
        msg_sh[idx] = (unsigned char)c;
    }
    __syncthreads();

    // ---- Gather phase ----
    // Thread t handles hid cols h4*4..h4*4+3 (float4) for rows rgrp*8..rgrp*8+7.
    // Within a warp: rgrp constant, h4 = lane -> per-row the 32 lanes read one
    // contiguous 512B slice of W1 (fully coalesced LDG.128).
    const int h4   = t & 31;     // float4 column index
    const int rgrp = t >> 5;     // warp id -> row group of 8

    float4 acc[8];
    {
        float4 bias1 = __ldg(&((const float4*)b1)[h4]);
        #pragma unroll
        for (int i = 0; i < 8; i++) acc[i] = bias1;
    }

    const float4* W1v = (const float4*)W1 + h4;   // + h4 (float4 units)
    #pragma unroll 1
    for (int p = 0; p < NPOS; p++) {
        // 8 chars for this warp's rows at this position (broadcast LDS)
        const uint2 mw = *(const uint2*)(msg_sh + p * 64 + rgrp * 8);
        unsigned lo = mw.x, hi = mw.y;
        const float4* Wp = W1v + (p << 13);       // + p*256*128/4
        #pragma unroll
        for (int r = 0; r < 4; r++) {
            int c = (lo >> (8 * r)) & 255;
            float4 w = __ldg(Wp + (c << 5));      // + c*128/4
            acc[r].x += w.x; acc[r].y += w.y; acc[r].z += w.z; acc[r].w += w.w;
        }
        #pragma unroll
        for (int r = 0; r < 4; r++) {
            int c = (hi >> (8 * r)) & 255;
            float4 w = __ldg(Wp + (c << 5));
            acc[4 + r].x += w.x; acc[4 + r].y += w.y;
            acc[4 + r].z += w.z; acc[4 + r].w += w.w;
        }
    }

    // elu + store h0 into hA as [r][k] (float4, conflict-free)
    #pragma unroll
    for (int i = 0; i < 8; i++) {
        float4 v;
        v.x = elu1(acc[i].x); v.y = elu1(acc[i].y);
        v.z = elu1(acc[i].z); v.w = elu1(acc[i].w);
        ((float4*)hA)[(rgrp * 8 + i) * 32 + h4] = v;
    }
    __syncthreads();   // hA complete; msg_sh no longer needed

    // ---- Dense layers: thread computes an 8-row x 4-col register tile ----
    const int j4 = t & 31;          // float4 column index (cols j4*4 .. j4*4+3)
    const int r0 = (t >> 5) * 8;    // 8 rows starting here

    const float* Wg[3] = {W2, W3, W4};
    const float* bg[3] = {b2, b3, b4};
    float4* Wsh4 = (float4*)Wsh;

    #pragma unroll 1
    for (int layer = 0; layer < 3; layer++) {
        const float* hin  = (layer == 1) ? hB : hA;
        float*       hout = (layer == 1) ? hA : hB;
        const bool   last = (layer == 2);

        // Stage weights (16 KB from L2)
        const float4* Wg4 = (const float4*)Wg[layer];
        for (int i = t; i < 4096; i += THREADS) Wsh4[i] = __ldg(&Wg4[i]);
        __syncthreads();

        float4 bias = __ldg(&((const float4*)bg[layer])[j4]);
        float a0[8], a1[8], a2[8], a3[8];
        #pragma unroll
        for (int r = 0; r < 8; r++) {
            a0[r] = bias.x; a1[r] = bias.y; a2[r] = bias.z; a3[r] = bias.w;
        }

        #pragma unroll 4
        for (int k = 0; k < HID; k++) {
            float4 w = Wsh4[k * 32 + j4];            // 128B per warp, conflict-free
            #pragma unroll
            for (int r = 0; r < 8; r++) {
                float hv = hin[(r0 + r) * HID + k];  // warp-broadcast
                a0[r] = fmaf(hv, w.x, a0[r]);
                a1[r] = fmaf(hv, w.y, a1[r]);
                a2[r] = fmaf(hv, w.z, a2[r]);
                a3[r] = fmaf(hv, w.w, a3[r]);
            }
        }

        if (!last) {
            #pragma unroll
            for (int r = 0; r < 8; r++) {
                float4 v;
                v.x = elu1(a0[r]); v.y = elu1(a1[r]);
                v.z = elu1(a2[r]); v.w = elu1(a3[r]);
                ((float4*)hout)[(r0 + r) * 32 + j4] = v;
            }
            __syncthreads();   // hout complete + Wsh reads done before next stage
        } else {
            #pragma unroll
            for (int r = 0; r < 8; r++) {
                int row = row0 + r0 + r;
                if (row < B) {
                    float4 v;
                    v.x = elu1(a0[r]); v.y = elu1(a1[r]);
                    v.z = elu1(a2[r]); v.w = elu1(a3[r]);
                    ((float4*)out)[row * 32 + j4] = v;
                }
            }
        }
    }
}

extern "C" void kernel_launch(void* const* d_in, const int* in_sizes, int n_in,
                              void* d_out, int out_size)
{
    const int*   msg = (const int*)  d_in[0];
    const float* W1  = (const float*)d_in[1];
    const float* b1  = (const float*)d_in[2];
    const float* W2  = (const float*)d_in[3];
    const float* b2  = (const float*)d_in[4];
    const float* W3  = (const float*)d_in[5];
    const float* b3  = (const float*)d_in[6];
    const float* W4  = (const float*)d_in[7];
    const float* b4  = (const float*)d_in[8];
    float* out = (float*)d_out;

    const int B = in_sizes[0] / NPOS;   // 8192

    cudaFuncSetAttribute(fused_kernel,
                         cudaFuncAttributeMaxDynamicSharedMemorySize, SMEM_BYTES);

    detect_kernel<<<1, 32>>>(msg);

    int grid = (B + TILE - 1) / TILE;   // 128 CTAs
    fused_kernel<<<grid, THREADS, SMEM_BYTES>>>(msg, W1, b1, W2, b2, W3, b3,
                                                W4, b4, out, B);
}

// round 3
// speedup vs baseline: 1.0497x; 1.0497x over previous
#include <cuda_runtime.h>
#include <math.h>
#include <stdint.h>

#define NPOS    80
#define HID     128
#define TILE    32      // rows per CTA
#define THREADS 256

// Shared memory (dynamic, 96 KB):
//   [0     , 16384) floats : Wsh (current layer weights, 128x128 row-major)
//                            -- aliased by msg bytes (2560B) during gather
//   [16384 , 20480) floats : hA (32 x 128)
//   [20480 , 24576) floats : hB (32 x 128)
#define SMEM_FLOATS 24576
#define SMEM_BYTES  (SMEM_FLOATS * 4)

__device__ int g_msg_is64;

__global__ void detect_kernel(const int* __restrict__ msg) {
    int t = threadIdx.x;
    int v = 0;
    #pragma unroll 4
    for (int i = t; i < 2048; i += 32) v |= msg[2 * i + 1];
    unsigned ball = __ballot_sync(0xFFFFFFFFu, v != 0);
    if (t == 0) g_msg_is64 = (ball == 0u) ? 1 : 0;
}

__device__ __forceinline__ float elu1(float x) {
    return x > 0.0f ? x : expm1f(x);
}

// ---- f32x2 packed helpers ----
__device__ __forceinline__ unsigned long long pk2(float lo, float hi) {
    unsigned long long r;
    asm("mov.b64 %0, {%1, %2};" : "=l"(r) : "f"(lo), "f"(hi));
    return r;
}
__device__ __forceinline__ void upk2(unsigned long long v, float& lo, float& hi) {
    asm("mov.b64 {%0, %1}, %2;" : "=f"(lo), "=f"(hi) : "l"(v));
}
__device__ __forceinline__ void fma2(unsigned long long& d,
                                     unsigned long long a, unsigned long long b) {
    asm("fma.rn.f32x2 %0, %1, %2, %0;" : "+l"(d) : "l"(a), "l"(b));
}
__device__ __forceinline__ void add2(unsigned long long& d, unsigned long long a) {
    asm("add.rn.f32x2 %0, %0, %1;" : "+l"(d) : "l"(a));
}

__global__ __launch_bounds__(THREADS, 2)
void fused_kernel(const int* __restrict__ msg,
                  const float* __restrict__ W1, const float* __restrict__ b1,
                  const float* __restrict__ W2, const float* __restrict__ b2,
                  const float* __restrict__ W3, const float* __restrict__ b3,
                  const float* __restrict__ W4, const float* __restrict__ b4,
                  float* __restrict__ out, int B)
{
    extern __shared__ float smem[];
    float*  Wsh = smem;
    float4* Wsh4 = (float4*)smem;
    float4* hA4 = (float4*)(smem + 16384);
    float4* hB4 = (float4*)(smem + 20480);
    unsigned char* msg_sh = (unsigned char*)smem;   // 2560 B, aliases Wsh

    const int t    = threadIdx.x;
    const int row0 = blockIdx.x * TILE;
    const int is64 = g_msg_is64;

    // ---- Stage message tile as bytes, layout [p][r] ----
    for (int idx = t; idx < NPOS * TILE; idx += THREADS) {
        int p = idx >> 5;         // position 0..79
        int r = idx & 31;         // local row
        int row = row0 + r;
        int c = 0;
        if (row < B) {
            int gi = row * NPOS + p;
            c = is64 ? msg[2 * gi] : msg[gi];
        }
        msg_sh[idx] = (unsigned char)c;
    }
    __syncthreads();

    // ---- Gather phase ----
    // lane = float4 hid column h4; warp wr handles rows wr*4 .. wr*4+3.
    // Per (row, p): 32 lanes read one contiguous 512B W1 row (coalesced LDG.128).
    const int h4 = t & 31;
    const int wr = t >> 5;

    unsigned long long acc[4][2];
    {
        float4 bias1 = __ldg(&((const float4*)b1)[h4]);
        unsigned long long blo = pk2(bias1.x, bias1.y);
        unsigned long long bhi = pk2(bias1.z, bias1.w);
        #pragma unroll
        for (int i = 0; i < 4; i++) { acc[i][0] = blo; acc[i][1] = bhi; }
    }

    const float4* W1v = (const float4*)W1 + h4;
    #pragma unroll 2
    for (int p = 0; p < NPOS; p++) {
        unsigned c4 = *(const unsigned*)(msg_sh + p * TILE + wr * 4); // 4 chars, broadcast
        const float4* Wp = W1v + (p << 13);     // + p*256*128/4
        #pragma unroll
        for (int i = 0; i < 4; i++) {
            int c = (c4 >> (8 * i)) & 255;
            float4 w = __ldg(Wp + (c << 5));    // + c*128/4
            ulonglong2 uw = *(ulonglong2*)&w;
            add2(acc[i][0], uw.x);
            add2(acc[i][1], uw.y);
        }
    }

    // elu + store h0 into hA[r][k] (float4, conflict-free)
    #pragma unroll
    for (int i = 0; i < 4; i++) {
        float4 v;
        upk2(acc[i][0], v.x, v.y);
        upk2(acc[i][1], v.z, v.w);
        v.x = elu1(v.x); v.y = elu1(v.y); v.z = elu1(v.z); v.w = elu1(v.w);
        hA4[(wr * 4 + i) * 32 + h4] = v;
    }
    __syncthreads();   // hA complete; msg_sh dead

    // ---- Dense layers ----
    // Thread tile: 4 rows x 4 cols. Accumulators are f32x2 paired over k-parity
    // (lo = even-k partial + bias, hi = odd-k partial); horizontal add at end.
    const int j4 = t & 31;          // float4 column index
    const int r0 = (t >> 5) * 4;    // 4 rows starting here

    const float* Wg[3] = {W2, W3, W4};
    const float* bg[3] = {b2, b3, b4};

    #pragma unroll 1
    for (int layer = 0; layer < 3; layer++) {
        const float4* hin  = (layer == 1) ? hB4 : hA4;
        float4*       hout = (layer == 1) ? hA4 : hB4;
        const bool    last = (layer == 2);

        // Stage weights row-major (16 KB from L2, coalesced, conflict-free)
        const float4* Wg4 = (const float4*)Wg[layer];
        #pragma unroll 4
        for (int i = t; i < 4096; i += THREADS) Wsh4[i] = __ldg(&Wg4[i]);
        __syncthreads();

        unsigned long long a[4][4];   // [row][col], f32x2 over k-parity
        {
            float4 bias = __ldg(&((const float4*)bg[layer])[j4]);
            #pragma unroll
            for (int r = 0; r < 4; r++) {
                a[r][0] = pk2(bias.x, 0.0f);
                a[r][1] = pk2(bias.y, 0.0f);
                a[r][2] = pk2(bias.z, 0.0f);
                a[r][3] = pk2(bias.w, 0.0f);
            }
        }

        #pragma unroll 4
        for (int k4 = 0; k4 < 32; k4++) {
            // weights: rows 4k4..4k4+3, this thread's 4 cols
            float4 w0 = Wsh4[(4 * k4 + 0) * 32 + j4];
            float4 w1 = Wsh4[(4 * k4 + 1) * 32 + j4];
            float4 w2 = Wsh4[(4 * k4 + 2) * 32 + j4];
            float4 w3 = Wsh4[(4 * k4 + 3) * 32 + j4];
            // k-pair packed weights: (w[k],w[k+1]) per col
            unsigned long long wp0[4], wp1[4];
            wp0[0] = pk2(w0.x, w1.x); wp0[1] = pk2(w0.y, w1.y);
            wp0[2] = pk2(w0.z, w1.z); wp0[3] = pk2(w0.w, w1.w);
            wp1[0] = pk2(w2.x, w3.x); wp1[1] = pk2(w2.y, w3.y);
            wp1[2] = pk2(w2.z, w3.z); wp1[3] = pk2(w2.w, w3.w);
            #pragma unroll
            for (int r = 0; r < 4; r++) {
                // h[r][4k4..4k4+3] as two f32x2 (warp-broadcast LDS.128)
                ulonglong2 hv = *(const ulonglong2*)&hin[(r0 + r) * 32 + k4];
                fma2(a[r][0], hv.x, wp0[0]);
                fma2(a[r][1], hv.x, wp0[1]);
                fma2(a[r][2], hv.x, wp0[2]);
                fma2(a[r][3], hv.x, wp0[3]);
                fma2(a[r][0], hv.y, wp1[0]);
                fma2(a[r][1], hv.y, wp1[1]);
                fma2(a[r][2], hv.y, wp1[2]);
                fma2(a[r][3], hv.y, wp1[3]);
            }
        }

        if (!last) {
            #pragma unroll
            for (int r = 0; r < 4; r++) {
                float4 v; float lo, hi;
                upk2(a[r][0], lo, hi); v.x = elu1(lo + hi);
                upk2(a[r][1], lo, hi); v.y = elu1(lo + hi);
                upk2(a[r][2], lo, hi); v.z = elu1(lo + hi);
                upk2(a[r][3], lo, hi); v.w = elu1(lo + hi);
                hout[(r0 + r) * 32 + j4] = v;
            }
            __syncthreads();   // hout complete + Wsh reads done
        } else {
            #pragma unroll
            for (int r = 0; r < 4; r++) {
                int row = row0 + r0 + r;
                if (row < B) {
                    float4 v; float lo, hi;
                    upk2(a[r][0], lo, hi); v.x = elu1(lo + hi);
                    upk2(a[r][1], lo, hi); v.y = elu1(lo + hi);
                    upk2(a[r][2], lo, hi); v.z = elu1(lo + hi);
                    upk2(a[r][3], lo, hi); v.w = elu1(lo + hi);
                    ((float4*)out)[row * 32 + j4] = v;
                }
            }
        }
    }
}

extern "C" void kernel_launch(void* const* d_in, const int* in_sizes, int n_in,
                              void* d_out, int out_size)
{
    const int*   msg = (const int*)  d_in[0];
    const float* W1  = (const float*)d_in[1];
    const float* b1  = (const float*)d_in[2];
    const float* W2  = (const float*)d_in[3];
    const float* b2  = (const float*)d_in[4];
    const float* W3  = (const float*)d_in[5];
    const float* b3  = (const float*)d_in[6];
    const float* W4  = (const float*)d_in[7];
    const float* b4  = (const float*)d_in[8];
    float* out = (float*)d_out;

    const int B = in_sizes[0] / NPOS;   // 8192

    cudaFuncSetAttribute(fused_kernel,
                         cudaFuncAttributeMaxDynamicSharedMemorySize, SMEM_BYTES);

    detect_kernel<<<1, 32>>>(msg);

    int grid = (B + TILE - 1) / TILE;   // 256 CTAs
    fused_kernel<<<grid, THREADS, SMEM_BYTES>>>(msg, W1, b1, W2, b2, W3, b3,
                                                W4, b4, out, B);
}